// round 16
// baseline (speedup 1.0000x reference)
#include <cuda_runtime.h>
#include <cuda_fp16.h>
#include <cstdint>

// ---------------------------------------------------------------------------
static constexpr int B_ = 16;
static constexpr int N_ = 2048;
static constexpr int D_ = 64;
static constexpr int NW = N_ / 32;        // 64 mask words per row
// 1/sqrt(2048) * log2(e), folded into Q at convert time; scores then feed
// ex2.approx directly:  exp(q.k/sqrt(N)) == exp2((q*Q2SCALE).k)
#define Q2SCALE_F 0.0318793577f

// Scratch (__device__ globals; no runtime allocation)
__device__ __half    g_Qh[(size_t)B_ * N_ * D_];   // 4 MB  (pre-scaled)
__device__ __half    g_Kh[(size_t)B_ * N_ * D_];   // 4 MB
__device__ __half    g_Vs[(size_t)B_ * N_ * D_];   // 4 MB  V' = V * rd[m]
__device__ __half    g_E [(size_t)B_ * N_ * N_];   // 134 MB  E^T[b][m][n], masked exp2
__device__ unsigned  g_mbT[(size_t)B_ * N_ * NW];  // mask bits, word over n

// ---------------------------------------------------------------------------
__device__ __forceinline__ uint32_t smem_u32(const void* p) {
    uint32_t a;
    asm("{ .reg .u64 t; cvta.to.shared.u64 t, %1; cvt.u32.u64 %0, t; }" : "=r"(a) : "l"(p));
    return a;
}
// NOTE: must be called UNCONDITIONALLY (straight-line code). Inline asm cannot
// be speculated by NVVM; putting it under a ternary/if creates divergent
// branches (the R10 regression). Select/mask AFTER the call.
__device__ __forceinline__ float ex2f(float x) {
    float r; asm("ex2.approx.f32 %0, %1;" : "=f"(r) : "f"(x)); return r;
}
__device__ __forceinline__ void ldsm_x4(uint32_t a[4], uint32_t addr) {
    asm volatile("ldmatrix.sync.aligned.m8n8.x4.shared.b16 {%0,%1,%2,%3}, [%4];"
        : "=r"(a[0]), "=r"(a[1]), "=r"(a[2]), "=r"(a[3]) : "r"(addr));
}
__device__ __forceinline__ void ldsm_x4t(uint32_t a[4], uint32_t addr) {
    asm volatile("ldmatrix.sync.aligned.m8n8.x4.trans.shared.b16 {%0,%1,%2,%3}, [%4];"
        : "=r"(a[0]), "=r"(a[1]), "=r"(a[2]), "=r"(a[3]) : "r"(addr));
}
__device__ __forceinline__ void mma16816(float c[4], const uint32_t a[4], const uint32_t b[2]) {
    asm volatile(
        "mma.sync.aligned.m16n8k16.row.col.f32.f16.f16.f32 "
        "{%0,%1,%2,%3}, {%4,%5,%6,%7}, {%8,%9}, {%0,%1,%2,%3};"
        : "+f"(c[0]), "+f"(c[1]), "+f"(c[2]), "+f"(c[3])
        : "r"(a[0]), "r"(a[1]), "r"(a[2]), "r"(a[3]), "r"(b[0]), "r"(b[1]));
}
__device__ __forceinline__ void cp16(uint32_t dst, const void* src) {
    asm volatile("cp.async.cg.shared.global [%0], [%1], 16;" :: "r"(dst), "l"(src));
}
__device__ __forceinline__ void cp_commit() { asm volatile("cp.async.commit_group;" ::: "memory"); }
__device__ __forceinline__ void cp_wait0()  { asm volatile("cp.async.wait_group 0;"  ::: "memory"); }

// ---------------------------------------------------------------------------
// Prep 1: pack int32 mask into transposed bitmask (word over n) — one read.
__global__ void pack_mask_kernel(const int* __restrict__ mask) {
    const int warp = blockIdx.x * 8 + (threadIdx.x >> 5);
    const int lane = threadIdx.x & 31;
    const int m_t = warp & 63, n_t = (warp >> 6) & 63, b = warp >> 12;
    const int* src = mask + ((size_t)b * N_ + n_t * 32) * N_ + m_t * 32 + lane;
    unsigned tw = 0;
    #pragma unroll
    for (int i = 0; i < 32; i++) {
        unsigned bal = __ballot_sync(0xffffffffu, src[(size_t)i * N_] != 0);
        tw |= ((bal >> lane) & 1u) << i;
    }
    g_mbT[((size_t)b * N_ + m_t * 32 + lane) * NW + n_t] = tw;
}

// Prep 2: q (pre-scaled by SCALE*log2e), k -> fp16
__global__ void convert_qk_kernel(const float* __restrict__ q, const float* __restrict__ k) {
    size_t i = (size_t)blockIdx.x * 256 + threadIdx.x;
    g_Qh[i] = __float2half_rn(q[i] * Q2SCALE_F);
    g_Kh[i] = __float2half_rn(k[i]);
}

// ---------------------------------------------------------------------------
// Colsum+store: per (b, 64 m-rows): S^T = K·Q^T via HMMA over all n,
// masked exp2 -> (a) per-lane column sums -> rd, (b) E^T tiles staged through
// a DOUBLE-BUFFERED smem tile; buffer c-1 is drained to g_E while chunk c
// computes (one barrier per chunk). Then V' = V*rd for this block's rows.
__global__ void __launch_bounds__(128, 4) colsum_kernel(const float* __restrict__ v) {
    __shared__ __half Kst[64 * 72];
    __shared__ __half Qs[2][64 * 72];
    __shared__ __half Est[2][64 * 72];       // double-buffered E^T staging
    __shared__ float rdsm[64];
    const int tid = threadIdx.x, w = tid >> 5, lane = tid & 31;
    const int b = blockIdx.y, m0 = blockIdx.x * 64;

    // prefetch Q chunk 0 (async)
    {
        const int4* Qg = (const int4*)(g_Qh + (size_t)b * N_ * D_);
        #pragma unroll 4
        for (int i = tid; i < 512; i += 128) {
            int r = i >> 3, j = i & 7;
            cp16(smem_u32(&Qs[0][r * 72 + j * 8]), Qg + i);
        }
        cp_commit();
    }
    // K tile (plain loads)
    {
        const int4* Kg = (const int4*)(g_Kh + ((size_t)b * N_ + m0) * D_);
        #pragma unroll 4
        for (int i = tid; i < 512; i += 128) {
            int r = i >> 3, j = i & 7;
            *(int4*)&Kst[r * 72 + j * 8] = Kg[i];
        }
    }
    cp_wait0();
    __syncthreads();

    uint32_t Af[4][4];   // A = K rows (m), 4 k16 steps over D=64
    {
        int mat = lane >> 3;
        int row = w * 16 + (mat & 1) * 8 + (lane & 7);
        int colb = (mat >> 1) * 8;
        #pragma unroll
        for (int ks = 0; ks < 4; ks++)
            ldsm_x4(Af[ks], smem_u32(&Kst[row * 72 + ks * 16 + colb]));
    }

    const int mr0 = m0 + w * 16 + (lane >> 2);
    const unsigned* mT0 = g_mbT + ((size_t)b * N_ + mr0) * NW;
    const unsigned* mT1 = mT0 + 8 * NW;
    float acc0 = 0.f, acc1 = 0.f;

    const int r4  = (lane >> 4) * 8 + (lane & 7);       // row within 16-row pair
    const int c4  = ((lane >> 3) & 1) * 8;              // 8-col half select
    const int sh0 = (lane & 3) * 2;
    const int rl  = w * 16 + (lane >> 2);               // local m row for staging
    const int drn_r = tid >> 1, drn_h = tid & 1;        // drain mapping

    __half* Egbase = g_E + ((size_t)b * N_ + m0) * N_;

    for (int c = 0; c < 32; c++) {
        if (c + 1 < 32) {   // prefetch next chunk
            const int4* Qg = (const int4*)(g_Qh + ((size_t)b * N_ + (c + 1) * 64) * D_);
            #pragma unroll 4
            for (int i = tid; i < 512; i += 128) {
                int r = i >> 3, j = i & 7;
                cp16(smem_u32(&Qs[(c + 1) & 1][r * 72 + j * 8]), Qg + i);
            }
        }
        cp_commit();

        // drain PREVIOUS chunk's Est buffer (complete per the loop-end barrier);
        // overlaps with this chunk's MMA/exp below. Buffer (c-1)&1 is not
        // rewritten until iteration c+1, after the next barrier -> race-free.
        if (c > 0) {
            __half* Eg = Egbase + (c - 1) * 64;
            const int4* s = (const int4*)&Est[(c - 1) & 1][drn_r * 72 + drn_h * 32];
            int4* d = (int4*)(Eg + (size_t)drn_r * N_ + drn_h * 32);
            d[0] = s[0]; d[1] = s[1]; d[2] = s[2]; d[3] = s[3];
        }

        const __half* Qb = Qs[c & 1];
        // pre-shifted mask words: per-element tests are constant-position
        const unsigned u0 = mT0[c * 2] >> sh0, u1 = mT0[c * 2 + 1] >> sh0;
        const unsigned v0 = mT1[c * 2] >> sh0, v1 = mT1[c * 2 + 1] >> sh0;

        #pragma unroll
        for (int j2 = 0; j2 < 4; j2++) {
            float c0[4] = {0.f, 0.f, 0.f, 0.f}, c1[4] = {0.f, 0.f, 0.f, 0.f};
            #pragma unroll
            for (int ks = 0; ks < 4; ks++) {
                uint32_t B4[4];
                ldsm_x4(B4, smem_u32(&Qb[(j2 * 16 + r4) * 72 + ks * 16 + c4]));
                mma16816(c0, Af[ks], B4);
                mma16816(c1, Af[ks], B4 + 2);
            }
            const unsigned ua = (j2 < 2) ? u0 : u1;
            const unsigned ub = (j2 < 2) ? v0 : v1;
            const int bb = (j2 & 1) * 16;
            // ex2 computed unconditionally; masked values zeroed by select.
            float e00 = ex2f(c0[0]), e01 = ex2f(c0[1]);
            float e02 = ex2f(c0[2]), e03 = ex2f(c0[3]);
            float e10 = ex2f(c1[0]), e11 = ex2f(c1[1]);
            float e12 = ex2f(c1[2]), e13 = ex2f(c1[3]);
            if ((ua >> bb) & 1)       e00 = 0.f;
            if ((ua >> (bb + 1)) & 1) e01 = 0.f;
            if ((ub >> bb) & 1)       e02 = 0.f;
            if ((ub >> (bb + 1)) & 1) e03 = 0.f;
            if ((ua >> (bb + 8)) & 1) e10 = 0.f;
            if ((ua >> (bb + 9)) & 1) e11 = 0.f;
            if ((ub >> (bb + 8)) & 1) e12 = 0.f;
            if ((ub >> (bb + 9)) & 1) e13 = 0.f;
            // sums (x+0 is exact -> same order/rounding as predicated adds)
            acc0 += e00; acc0 += e01; acc1 += e02; acc1 += e03;
            acc0 += e10; acc0 += e11; acc1 += e12; acc1 += e13;
            // stage E^T tile: row = m local, col = n local (half2 granular)
            __half2* E2 = (__half2*)Est[c & 1];
            const int cb = j2 * 8 + (lane & 3);   // half2 col index (n = j2*16+sh0)
            E2[rl * 36 + cb]           = __floats2half2_rn(e00, e01);
            E2[(rl + 8) * 36 + cb]     = __floats2half2_rn(e02, e03);
            E2[rl * 36 + cb + 4]       = __floats2half2_rn(e10, e11);
            E2[(rl + 8) * 36 + cb + 4] = __floats2half2_rn(e12, e13);
        }
        cp_wait0();
        __syncthreads();      // Est[c&1] complete + next Q ready + drain target safe
    }

    // final drain: chunk 31's buffer (loop-end barrier already passed)
    {
        __half* Eg = Egbase + 31 * 64;
        const int4* s = (const int4*)&Est[31 & 1][drn_r * 72 + drn_h * 32];
        int4* d = (int4*)(Eg + (size_t)drn_r * N_ + drn_h * 32);
        d[0] = s[0]; d[1] = s[1]; d[2] = s[2]; d[3] = s[3];
    }

    acc0 += __shfl_xor_sync(0xffffffffu, acc0, 1);
    acc0 += __shfl_xor_sync(0xffffffffu, acc0, 2);
    acc1 += __shfl_xor_sync(0xffffffffu, acc1, 1);
    acc1 += __shfl_xor_sync(0xffffffffu, acc1, 2);
    if ((lane & 3) == 0) {
        rdsm[w * 16 + (lane >> 2)]     = 1.0f / acc0;
        rdsm[w * 16 + (lane >> 2) + 8] = 1.0f / acc1;
    }
    __syncthreads();

    // Fused: V' = V * rd for this block's 64 m-rows
    {
        const float2* Vg = (const float2*)(v + ((size_t)b * N_ + m0) * D_);
        __half2* Vd = (__half2*)(g_Vs + ((size_t)b * N_ + m0) * D_);
        #pragma unroll 4
        for (int i = tid; i < 64 * 32; i += 128) {
            const float rd = rdsm[i >> 5];
            float2 f = Vg[i];
            Vd[i] = __floats2half2_rn(f.x * rd, f.y * rd);
        }
    }
}

// ---------------------------------------------------------------------------
// Out: pure GEMM.  out[n,d] = sum_m E[n,m] * V'[m,d].
// Per (b, 64 n-rows): loop m chunks of 64 (double-buffered cp.async):
//   A-frags from E^T tile via ldsm.x4.trans, B-frags from V' via ldsm.x4.trans.
__global__ void __launch_bounds__(128, 6) out_kernel(float* __restrict__ out) {
    extern __shared__ __half dsm[];
    __half* Etb = dsm;                 // 2 x 64*72  (E^T chunk: rows m, cols n)
    __half* Vtb = dsm + 2 * 64 * 72;   // 2 x 64*72  (V' chunk: rows m, cols d)
    const int tid = threadIdx.x, w = tid >> 5, lane = tid & 31;
    const int b = blockIdx.y, n0 = blockIdx.x * 64;

    const int4* Eg = (const int4*)(g_E + (size_t)b * N_ * N_ + n0);  // row stride 256 int4
    const int4* Vg = (const int4*)(g_Vs + (size_t)b * N_ * D_);      // contiguous rows

    // prefetch chunk 0
    #pragma unroll 4
    for (int i = tid; i < 512; i += 128) {
        int r = i >> 3, j = i & 7;
        cp16(smem_u32(&Etb[r * 72 + j * 8]), Eg + (size_t)r * 256 + j);
        cp16(smem_u32(&Vtb[r * 72 + j * 8]), Vg + i);
    }
    cp_commit();
    // chunk-0 visibility barrier (R13 NaN lesson): first ldsm of buffer 0
    // must not race its own cp.async.
    cp_wait0();
    __syncthreads();

    float o[8][4];
    #pragma unroll
    for (int dt = 0; dt < 8; dt++)
        #pragma unroll
        for (int e = 0; e < 4; e++) o[dt][e] = 0.f;

    // A-frag (E[n][m]) ldsm.trans addressing into E^T tile:
    //   tiles t=lane>>3: t0:(m0-7,n+0) t1:(m0-7,n+8) t2:(m8-15,n+0) t3:(m8-15,n+8)
    const int amr = (lane & 7) + ((lane >> 4) & 1) * 8;       // m row within 16-block
    const int anc = w * 16 + ((lane >> 3) & 1) * 8;           // n col (warp's 16 rows)
    const int vr  = lane & 15;                                // V' k(m) row
    const int vco = (lane >> 4) * 8;                          // V' d col block

    for (int c = 0; c < 32; c++) {
        if (c + 1 < 32) {   // prefetch next E^T/V' chunk
            const int4* Egn = Eg + (size_t)(c + 1) * 64 * 256;
            const int4* Vgn = Vg + (c + 1) * 512;
            const int buf = ((c + 1) & 1) * 64 * 72;
            #pragma unroll 4
            for (int i = tid; i < 512; i += 128) {
                int r = i >> 3, j = i & 7;
                cp16(smem_u32(&Etb[buf + r * 72 + j * 8]), Egn + (size_t)r * 256 + j);
                cp16(smem_u32(&Vtb[buf + r * 72 + j * 8]), Vgn + i);
            }
        }
        cp_commit();

        const __half* Eb = Etb + (c & 1) * 64 * 72;
        const __half* Vb = Vtb + (c & 1) * 64 * 72;

        uint32_t Ae[4][4];
        #pragma unroll
        for (int ks = 0; ks < 4; ks++)
            ldsm_x4t(Ae[ks], smem_u32(&Eb[(ks * 16 + amr) * 72 + anc]));

        #pragma unroll
        for (int ks = 0; ks < 4; ks++) {
            #pragma unroll
            for (int dt2 = 0; dt2 < 4; dt2++) {
                uint32_t V4[4];
                ldsm_x4t(V4, smem_u32(&Vb[(ks * 16 + vr) * 72 + dt2 * 16 + vco]));
                mma16816(o[2 * dt2],     Ae[ks], V4);
                mma16816(o[2 * dt2 + 1], Ae[ks], V4 + 2);
            }
        }
        cp_wait0();
        __syncthreads();
    }

    const int nr0 = n0 + w * 16 + (lane >> 2);
    float* obase = out + ((size_t)b * N_ + nr0) * D_;
    const int col0 = (lane & 3) * 2;
    #pragma unroll
    for (int dt = 0; dt < 8; dt++) {
        *(float2*)&obase[dt * 8 + col0]          = make_float2(o[dt][0], o[dt][1]);
        *(float2*)&obase[8 * D_ + dt * 8 + col0] = make_float2(o[dt][2], o[dt][3]);
    }
}

// ---------------------------------------------------------------------------
extern "C" void kernel_launch(void* const* d_in, const int* in_sizes, int n_in,
                              void* d_out, int out_size)
{
    const float* q = (const float*)d_in[0];
    const float* k = (const float*)d_in[1];
    const float* v = (const float*)d_in[2];
    const int* mask = (const int*)d_in[3];
    float* out = (float*)d_out;

    cudaFuncSetAttribute(out_kernel, cudaFuncAttributeMaxDynamicSharedMemorySize, 36864);

    pack_mask_kernel<<<(B_ * 64 * 64) / 8, 256>>>(mask);
    convert_qk_kernel<<<(unsigned)(((size_t)B_ * N_ * D_) / 256), 256>>>(q, k);
    colsum_kernel<<<dim3(N_ / 64, B_), 128>>>(v);
    out_kernel<<<dim3(N_ / 64, B_), 128, 36864>>>(out);
}

// round 17
// speedup vs baseline: 1.1635x; 1.1635x over previous
#include <cuda_runtime.h>
#include <cuda_fp16.h>
#include <cstdint>

// ---------------------------------------------------------------------------
static constexpr int B_ = 16;
static constexpr int N_ = 2048;
static constexpr int D_ = 64;
static constexpr int NW = N_ / 32;        // 64 mask words per row
// 1/sqrt(2048) * log2(e), folded into Q at convert time; scores then feed
// ex2.approx directly:  exp(q.k/sqrt(N)) == exp2((q*Q2SCALE).k)
#define Q2SCALE_F 0.0318793577f

// Scratch (__device__ globals; no runtime allocation)
__device__ __half    g_Qh[(size_t)B_ * N_ * D_];   // 4 MB  (pre-scaled)
__device__ __half    g_Kh[(size_t)B_ * N_ * D_];   // 4 MB
__device__ __half    g_Vs[(size_t)B_ * N_ * D_];   // 4 MB  V' = V * rd[m]
// E stored as PV-A-FRAGMENT blob (not row-major): 134 MB.
// int4 index: ((b*32 + m_blk)*32 + n_chunk)*16 + w*4 + mt)*32 + lane
__device__ __half    g_E [(size_t)B_ * N_ * N_];
__device__ unsigned  g_mbN[(size_t)B_ * N_ * NW];  // mask bits, word over m

// ---------------------------------------------------------------------------
__device__ __forceinline__ uint32_t smem_u32(const void* p) {
    uint32_t a;
    asm("{ .reg .u64 t; cvta.to.shared.u64 t, %1; cvt.u32.u64 %0, t; }" : "=r"(a) : "l"(p));
    return a;
}
// Must be called UNCONDITIONALLY (R10 lesson: inline asm can't be speculated).
__device__ __forceinline__ float ex2f(float x) {
    float r; asm("ex2.approx.f32 %0, %1;" : "=f"(r) : "f"(x)); return r;
}
__device__ __forceinline__ void ldsm_x4(uint32_t a[4], uint32_t addr) {
    asm volatile("ldmatrix.sync.aligned.m8n8.x4.shared.b16 {%0,%1,%2,%3}, [%4];"
        : "=r"(a[0]), "=r"(a[1]), "=r"(a[2]), "=r"(a[3]) : "r"(addr));
}
__device__ __forceinline__ void ldsm_x4t(uint32_t a[4], uint32_t addr) {
    asm volatile("ldmatrix.sync.aligned.m8n8.x4.trans.shared.b16 {%0,%1,%2,%3}, [%4];"
        : "=r"(a[0]), "=r"(a[1]), "=r"(a[2]), "=r"(a[3]) : "r"(addr));
}
__device__ __forceinline__ void mma16816(float c[4], const uint32_t a[4], const uint32_t b[2]) {
    asm volatile(
        "mma.sync.aligned.m16n8k16.row.col.f32.f16.f16.f32 "
        "{%0,%1,%2,%3}, {%4,%5,%6,%7}, {%8,%9}, {%0,%1,%2,%3};"
        : "+f"(c[0]), "+f"(c[1]), "+f"(c[2]), "+f"(c[3])
        : "r"(a[0]), "r"(a[1]), "r"(a[2]), "r"(a[3]), "r"(b[0]), "r"(b[1]));
}
// A-operand passed as int4 (E-blob register buffer) — avoids address-of-reg.
__device__ __forceinline__ void mma16816_i4(float c[4], const int4& a, const uint32_t b[2]) {
    asm volatile(
        "mma.sync.aligned.m16n8k16.row.col.f32.f16.f16.f32 "
        "{%0,%1,%2,%3}, {%4,%5,%6,%7}, {%8,%9}, {%0,%1,%2,%3};"
        : "+f"(c[0]), "+f"(c[1]), "+f"(c[2]), "+f"(c[3])
        : "r"(a.x), "r"(a.y), "r"(a.z), "r"(a.w), "r"(b[0]), "r"(b[1]));
}
__device__ __forceinline__ uint32_t h2u(__half2 h) { return *reinterpret_cast<uint32_t*>(&h); }
__device__ __forceinline__ void cp16(uint32_t dst, const void* src) {
    asm volatile("cp.async.cg.shared.global [%0], [%1], 16;" :: "r"(dst), "l"(src));
}
__device__ __forceinline__ void cp_commit() { asm volatile("cp.async.commit_group;" ::: "memory"); }
__device__ __forceinline__ void cp_wait0()  { asm volatile("cp.async.wait_group 0;"  ::: "memory"); }

// ---------------------------------------------------------------------------
// Prep 1: pack int32 mask into ROW-major bitmask (word over m) — one read.
__global__ void pack_mask_kernel(const int* __restrict__ mask) {
    const int warp = blockIdx.x * 8 + (threadIdx.x >> 5);
    const int lane = threadIdx.x & 31;
    const int m_t = warp & 63, n_t = (warp >> 6) & 63, b = warp >> 12;
    const int* src = mask + ((size_t)b * N_ + n_t * 32) * N_ + m_t * 32 + lane;
    unsigned* rowdst = g_mbN + ((size_t)b * N_ + n_t * 32) * NW + m_t;
    #pragma unroll
    for (int i = 0; i < 32; i++) {
        unsigned bal = __ballot_sync(0xffffffffu, src[(size_t)i * N_] != 0);
        if (lane == 0) rowdst[(size_t)i * NW] = bal;
    }
}

// Prep 2: q (pre-scaled by SCALE*log2e), k -> fp16
__global__ void convert_qk_kernel(const float* __restrict__ q, const float* __restrict__ k) {
    size_t i = (size_t)blockIdx.x * 256 + threadIdx.x;
    g_Qh[i] = __float2half_rn(q[i] * Q2SCALE_F);
    g_Kh[i] = __float2half_rn(k[i]);
}

// ---------------------------------------------------------------------------
// Colsum+store: CTA owns m-stripe [m0b*64, +64) of batch b; loops n chunks of
// 64 streaming Q. Computes S = Q·K^T in R11-out's exact orientation, masked
// exp2 -> (a) per-lane m-column partial sums (full reduce at end), (b) E in
// PV-A-fragment layout written straight from registers via coalesced STG.128.
// Finally V' = V*rd for this stripe's rows.
__global__ void __launch_bounds__(128, 4) colsum_kernel(const float* __restrict__ v) {
    __shared__ __half Kst[64 * 72];
    __shared__ __half Qs[2][64 * 72];
    __shared__ float psum[4][64];
    __shared__ float rdsm[64];
    const int tid = threadIdx.x, w = tid >> 5, lane = tid & 31;
    const int b = blockIdx.y, m0b = blockIdx.x, m0 = m0b * 64;

    // prefetch Q chunk 0 (async)
    {
        const int4* Qg = (const int4*)(g_Qh + (size_t)b * N_ * D_);
        #pragma unroll 4
        for (int i = tid; i < 512; i += 128) {
            int r = i >> 3, j = i & 7;
            cp16(smem_u32(&Qs[0][r * 72 + j * 8]), Qg + i);
        }
        cp_commit();
    }
    // K stripe tile (plain loads, fixed for whole kernel)
    {
        const int4* Kg = (const int4*)(g_Kh + ((size_t)b * N_ + m0) * D_);
        #pragma unroll 4
        for (int i = tid; i < 512; i += 128) {
            int r = i >> 3, j = i & 7;
            *(int4*)&Kst[r * 72 + j * 8] = Kg[i];
        }
    }
    cp_wait0();
    __syncthreads();

    const int r4  = (lane >> 4) * 8 + (lane & 7);   // K B-frag row select
    const int c4  = ((lane >> 3) & 1) * 8;
    const int sh0 = (lane & 3) * 2;
    const int q   = lane >> 2;

    float acc[16];
    #pragma unroll
    for (int i = 0; i < 16; i++) acc[i] = 0.f;

    int4* Eb = (int4*)g_E + (size_t)(b * 32 + m0b) * 16384;  // per (b,stripe) block

    for (int c = 0; c < 32; c++) {
        if (c + 1 < 32) {   // prefetch next Q chunk
            const int4* Qg = (const int4*)(g_Qh + ((size_t)b * N_ + (c + 1) * 64) * D_);
            #pragma unroll 4
            for (int i = tid; i < 512; i += 128) {
                int r = i >> 3, j = i & 7;
                cp16(smem_u32(&Qs[(c + 1) & 1][r * 72 + j * 8]), Qg + i);
            }
        }
        cp_commit();

        // Q A-frags for this warp's 16 n-rows of chunk c
        uint32_t Qa[4][4];
        {
            const __half* Qbuf = Qs[c & 1];
            int mat = lane >> 3;
            int row = w * 16 + (mat & 1) * 8 + (lane & 7);
            int colb = (mat >> 1) * 8;
            #pragma unroll
            for (int ks = 0; ks < 4; ks++)
                ldsm_x4(Qa[ks], smem_u32(&Qbuf[row * 72 + ks * 16 + colb]));
        }
        // mask words (row-major, this stripe's 2 m-words) for rows nr, nr+8
        const int nr = c * 64 + w * 16 + q;
        const unsigned* mr0 = g_mbN + ((size_t)b * N_ + nr) * NW + m0b * 2;
        const unsigned* mr1 = mr0 + 8 * NW;
        const unsigned u0 = mr0[0] >> sh0, u1 = mr0[1] >> sh0;
        const unsigned v0 = mr1[0] >> sh0, v1 = mr1[1] >> sh0;

        int4* Ec = Eb + ((size_t)c * 16 + w * 4) * 32 + lane;

        #pragma unroll
        for (int mt = 0; mt < 4; mt++) {
            float c0[4] = {0.f, 0.f, 0.f, 0.f}, c1[4] = {0.f, 0.f, 0.f, 0.f};
            #pragma unroll
            for (int ks = 0; ks < 4; ks++) {
                uint32_t B4[4];
                ldsm_x4(B4, smem_u32(&Kst[(mt * 16 + r4) * 72 + ks * 16 + c4]));
                mma16816(c0, Qa[ks], B4);
                mma16816(c1, Qa[ks], B4 + 2);
            }
            const unsigned ua = (mt < 2) ? u0 : u1;
            const unsigned ub = (mt < 2) ? v0 : v1;
            const int bb = (mt & 1) * 16;
            float e00 = ex2f(c0[0]), e01 = ex2f(c0[1]);
            float e02 = ex2f(c0[2]), e03 = ex2f(c0[3]);
            float e10 = ex2f(c1[0]), e11 = ex2f(c1[1]);
            float e12 = ex2f(c1[2]), e13 = ex2f(c1[3]);
            if ((ua >> bb) & 1)       e00 = 0.f;
            if ((ua >> (bb + 1)) & 1) e01 = 0.f;
            if ((ub >> bb) & 1)       e02 = 0.f;
            if ((ub >> (bb + 1)) & 1) e03 = 0.f;
            if ((ua >> (bb + 8)) & 1) e10 = 0.f;
            if ((ua >> (bb + 9)) & 1) e11 = 0.f;
            if ((ub >> (bb + 8)) & 1) e12 = 0.f;
            if ((ub >> (bb + 9)) & 1) e13 = 0.f;
            // m-column partial sums (e0x = rows nr/nr+8 at cols 2t0,2t0+1;
            // e1x = same rows at cols +8)
            acc[mt * 4 + 0] += e00 + e02;
            acc[mt * 4 + 1] += e01 + e03;
            acc[mt * 4 + 2] += e10 + e12;
            acc[mt * 4 + 3] += e11 + e13;
            // E in PV-A-frag layout (== R11's Ae[0..3]) -> coalesced STG.128
            uint32_t a0 = h2u(__floats2half2_rn(e00, e01));
            uint32_t a1 = h2u(__floats2half2_rn(e02, e03));
            uint32_t a2 = h2u(__floats2half2_rn(e10, e11));
            uint32_t a3 = h2u(__floats2half2_rn(e12, e13));
            Ec[mt * 32] = make_int4((int)a0, (int)a1, (int)a2, (int)a3);
        }
        cp_wait0();
        __syncthreads();
    }

    // reduce partial sums over the 8 q-lane groups (lanes differing in bits 2..4)
    #pragma unroll
    for (int i = 0; i < 16; i++) {
        acc[i] += __shfl_xor_sync(0xffffffffu, acc[i], 4);
        acc[i] += __shfl_xor_sync(0xffffffffu, acc[i], 8);
        acc[i] += __shfl_xor_sync(0xffffffffu, acc[i], 16);
    }
    if (lane < 4) {
        #pragma unroll
        for (int mt = 0; mt < 4; mt++)
            #pragma unroll
            for (int kk = 0; kk < 4; kk++)
                psum[w][mt * 16 + (kk >> 1) * 8 + 2 * lane + (kk & 1)] = acc[mt * 4 + kk];
    }
    __syncthreads();
    if (tid < 64) {
        float s = psum[0][tid] + psum[1][tid] + psum[2][tid] + psum[3][tid];
        rdsm[tid] = 1.0f / s;
    }
    __syncthreads();

    // Fused: V' = V * rd for this stripe's 64 m-rows
    {
        const float2* Vg = (const float2*)(v + ((size_t)b * N_ + m0) * D_);
        __half2* Vd = (__half2*)(g_Vs + ((size_t)b * N_ + m0) * D_);
        #pragma unroll 4
        for (int i = tid; i < 64 * 32; i += 128) {
            const float rd = rdsm[i >> 5];
            float2 f = Vg[i];
            Vd[i] = __floats2half2_rn(f.x * rd, f.y * rd);
        }
    }
}

// ---------------------------------------------------------------------------
// Out: pure GEMM, A-frags streamed from the E-blob via register-double-buffered
// coalesced LDG.128 (no smem, no ldsm for E). V' via cp.async + ldsm.trans.
__global__ void __launch_bounds__(128, 5) out_kernel(float* __restrict__ out) {
    extern __shared__ __half dsm[];
    __half* Vtb = dsm;                 // 2 x 64*72 (V' chunk)
    const int tid = threadIdx.x, w = tid >> 5, lane = tid & 31;
    const int b = blockIdx.y, bx = blockIdx.x, n0 = bx * 64;

    const int4* Vg = (const int4*)(g_Vs + (size_t)b * N_ * D_);
    // E-blob: for m-chunk mc, frag ks: idx = ((b*32+mc)*32 + bx)*16 + w*4 + ks)*32 + lane
    const int4* Ebase = (const int4*)g_E + ((size_t)(b * 32) * 32 + bx) * 16 * 32
                        + (w * 4) * 32 + lane;   // + mc*(32*16*32) + ks*32
    const size_t MCSTRIDE = (size_t)32 * 16 * 32;   // int4 per m-chunk step

    // prefetch V chunk 0; load E frags chunk 0
    #pragma unroll 4
    for (int i = tid; i < 512; i += 128) {
        int r = i >> 3, j = i & 7;
        cp16(smem_u32(&Vtb[r * 72 + j * 8]), Vg + i);
    }
    cp_commit();
    int4 Acur[4], Anext[4];
    #pragma unroll
    for (int ks = 0; ks < 4; ks++) Acur[ks] = Ebase[ks * 32];
    cp_wait0();
    __syncthreads();

    float o[8][4];
    #pragma unroll
    for (int dt = 0; dt < 8; dt++)
        #pragma unroll
        for (int e = 0; e < 4; e++) o[dt][e] = 0.f;

    const int vr  = lane & 15;
    const int vco = (lane >> 4) * 8;

    for (int mc = 0; mc < 32; mc++) {
        if (mc + 1 < 32) {   // prefetch next V chunk + next E frags
            const int4* Vgn = Vg + (mc + 1) * 512;
            const int buf = ((mc + 1) & 1) * 64 * 72;
            #pragma unroll 4
            for (int i = tid; i < 512; i += 128) {
                int r = i >> 3, j = i & 7;
                cp16(smem_u32(&Vtb[buf + r * 72 + j * 8]), Vgn + i);
            }
            const int4* En = Ebase + (size_t)(mc + 1) * MCSTRIDE;
            #pragma unroll
            for (int ks = 0; ks < 4; ks++) Anext[ks] = En[ks * 32];
        }
        cp_commit();

        const __half* Vb = Vtb + (mc & 1) * 64 * 72;
        #pragma unroll
        for (int ks = 0; ks < 4; ks++) {
            #pragma unroll
            for (int dt2 = 0; dt2 < 4; dt2++) {
                uint32_t V4[4];
                ldsm_x4t(V4, smem_u32(&Vb[(ks * 16 + vr) * 72 + dt2 * 16 + vco]));
                mma16816_i4(o[2 * dt2],     Acur[ks], V4);
                mma16816_i4(o[2 * dt2 + 1], Acur[ks], V4 + 2);
            }
        }
        #pragma unroll
        for (int ks = 0; ks < 4; ks++) Acur[ks] = Anext[ks];
        cp_wait0();
        __syncthreads();
    }

    const int nr0 = n0 + w * 16 + (lane >> 2);
    float* obase = out + ((size_t)b * N_ + nr0) * D_;
    const int col0 = (lane & 3) * 2;
    #pragma unroll
    for (int dt = 0; dt < 8; dt++) {
        *(float2*)&obase[dt * 8 + col0]          = make_float2(o[dt][0], o[dt][1]);
        *(float2*)&obase[8 * D_ + dt * 8 + col0] = make_float2(o[dt][2], o[dt][3]);
    }
}

// ---------------------------------------------------------------------------
extern "C" void kernel_launch(void* const* d_in, const int* in_sizes, int n_in,
                              void* d_out, int out_size)
{
    const float* q = (const float*)d_in[0];
    const float* k = (const float*)d_in[1];
    const float* v = (const float*)d_in[2];
    const int* mask = (const int*)d_in[3];
    float* out = (float*)d_out;

    cudaFuncSetAttribute(out_kernel, cudaFuncAttributeMaxDynamicSharedMemorySize, 18432);

    pack_mask_kernel<<<(B_ * 64 * 64) / 8, 256>>>(mask);
    convert_qk_kernel<<<(unsigned)(((size_t)B_ * N_ * D_) / 256), 256>>>(q, k);
    colsum_kernel<<<dim3(32, B_), 128>>>(v);
    out_kernel<<<dim3(N_ / 64, B_), 128, 18432>>>(out);
}